// round 4
// baseline (speedup 1.0000x reference)
#include <cuda_runtime.h>
#include <cstdint>

// Problem constants (match reference)
#define BB 32
#define QQ 512
#define RR 1024
#define LL 1536
#define DD 2048
#define MAXRL 1024
static __device__ __constant__ float GAMMA_C = 0.99f;
static __device__ __constant__ float LMBDA_C = 0.95f;

// ---------------- output layout (flattened tuple, float32) ----------------
// values(B*R), value_pad_mask(B*R), value_last_pos(B), scores(B),
// response_last_pos(B), kl(B*R), kl_rewards(B*R), advantages(B*R), returns(B*R)
#define OFF_VAL 0
#define OFF_VPM (BB*RR)
#define OFF_VLP (2*BB*RR)
#define OFF_SC  (2*BB*RR + BB)
#define OFF_RLP (2*BB*RR + 2*BB)
#define OFF_KL  (2*BB*RR + 3*BB)
#define OFF_KLR (3*BB*RR + 3*BB)
#define OFF_ADV (4*BB*RR + 3*BB)
#define OFF_RET (5*BB*RR + 3*BB)

// ---------------- device scratch (no allocations allowed) ----------------
__device__ float  g_adv[BB*RR];
__device__ int    g_rlp[BB];
__device__ int    g_vlp[BB];
__device__ int    g_pen[BB];
__device__ float  g_score[BB];
__device__ double g_psum[BB];
__device__ double g_psq[BB];
__device__ double g_pcnt[BB];

// ========================================================================
// K1: per-batch mask metadata. 1 block x 1024 threads; warp w -> batch w.
// Mask is a JAX bool marshalled as INT32 (one int per element).
// response_last_pos = last non-pad index (argmax of cumsum(~pad)), 0 if none.
// value_last_pos = rlp+1 if 0<rlp<MAXRL-1 else rlp.
// ========================================================================
__global__ void k_meta(const int* __restrict__ pad, float* __restrict__ out) {
    int w    = threadIdx.x >> 5;
    int lane = threadIdx.x & 31;
    const int* p = pad + (size_t)w * RR;
    int last = -1;
    int anyp = 0;
    #pragma unroll 8
    for (int j = lane; j < RR; j += 32) {
        int v = p[j];
        anyp |= v;
        if (!v) last = j;   // j strictly increasing per lane -> max survives
    }
    #pragma unroll
    for (int o = 16; o; o >>= 1) {
        last = max(last, __shfl_down_sync(0xffffffffu, last, o));
        anyp |= __shfl_down_sync(0xffffffffu, anyp, o);
    }
    if (lane == 0) {
        int rlp = last < 0 ? 0 : last;
        int vlp = (rlp > 0 && rlp < MAXRL - 1) ? rlp + 1 : rlp;
        g_rlp[w] = rlp;
        g_vlp[w] = vlp;
        g_pen[w] = !anyp;           // PENALISE_NO_EOS; MIN_RESPONSE_LEN==0 -> skipped
        out[OFF_VLP + w] = (float)vlp;
        out[OFF_RLP + w] = (float)rlp;
    }
}

// ========================================================================
// K2: values = hidden[:, Q-1 : L-1] . (w_base + w_adapter), masked by
// value_pad_mask. Warp-per-row: 8 rows per 256-thread block, float4 loads.
// Also emits value_pad_mask as float. This is the DRAM-roofline kernel.
// ========================================================================
__global__ void __launch_bounds__(256) k_values(
    const float* __restrict__ hidden, const float* __restrict__ wb,
    const float* __restrict__ wa, const int* __restrict__ pad,
    float* __restrict__ out)
{
    __shared__ float ws[DD];
    int tid = threadIdx.x;
    #pragma unroll
    for (int i = tid; i < DD; i += 256) ws[i] = wb[i] + wa[i];
    __syncthreads();

    int warp = tid >> 5, lane = tid & 31;
    int row = blockIdx.x * 8 + warp;          // 0 .. 32767
    int b = row >> 10, t = row & 1023;
    const float4* h  = (const float4*)(hidden + ((size_t)b * LL + (QQ - 1) + t) * DD);
    const float4* w4 = (const float4*)ws;

    float acc = 0.f;
    #pragma unroll
    for (int k = 0; k < 16; k++) {
        int i4 = lane + k * 32;
        float4 v = h[i4];
        float4 w = w4[i4];
        acc += v.x * w.x + v.y * w.y + v.z * w.z + v.w * w.w;
    }
    #pragma unroll
    for (int o = 16; o; o >>= 1) acc += __shfl_down_sync(0xffffffffu, acc, o);

    if (lane == 0) {
        int vpm = (pad[(size_t)b * RR + t] != 0) && (t != g_vlp[b]);
        out[OFF_VAL + row] = vpm ? 0.f : acc;
        out[OFF_VPM + row] = vpm ? 1.f : 0.f;
    }
}

// ========================================================================
// K2b: scores[b] = hidden[b, rlp[b]+Q] . w_base, with no-EOS penalty.
// 32 blocks x 256 threads (tiny).
// ========================================================================
__global__ void __launch_bounds__(256) k_scores(
    const float* __restrict__ hidden, const float* __restrict__ wb,
    float* __restrict__ out)
{
    int b = blockIdx.x, tid = threadIdx.x;
    int pos = QQ + g_rlp[b];
    const float4* h  = (const float4*)(hidden + ((size_t)b * LL + pos) * DD);
    const float4* w4 = (const float4*)wb;
    float acc = 0.f;
    #pragma unroll
    for (int i = tid; i < DD / 4; i += 256) {
        float4 v = h[i]; float4 w = w4[i];
        acc += v.x * w.x + v.y * w.y + v.z * w.z + v.w * w.w;
    }
    #pragma unroll
    for (int o = 16; o; o >>= 1) acc += __shfl_down_sync(0xffffffffu, acc, o);
    __shared__ float red[8];
    if ((tid & 31) == 0) red[tid >> 5] = acc;
    __syncthreads();
    if (tid == 0) {
        float s = 0.f;
        #pragma unroll
        for (int i = 0; i < 8; i++) s += red[i];
        if (g_pen[b]) s = -3.0f;   // REWARD_PENALTY
        g_score[b] = s;
        out[OFF_SC + b] = s;
    }
}

// ========================================================================
// K3: per-batch KL / rewards / GAE (weighted Kogge-Stone suffix scan) /
// returns, plus deterministic per-batch masked double partial sums.
// One block per batch, 1024 threads.
// ========================================================================
__global__ void __launch_bounds__(1024) k_gae(
    const float* __restrict__ gen, const float* __restrict__ ref,
    const int* __restrict__ pad, float* __restrict__ out)
{
    __shared__ float s_v[RR];
    __shared__ float s_a[RR];
    __shared__ double s_red[3][32];

    int b = blockIdx.x, t = threadIdx.x;
    int idx = b * RR + t;

    float v = out[OFF_VAL + idx];       // masked values written by K2
    s_v[t] = v;
    float kl  = gen[idx] - ref[idx];
    float klr = -0.1f * kl;             // KL_COEFF
    out[OFF_KL  + idx] = kl;
    out[OFF_KLR + idx] = klr;
    __syncthreads();

    float vn = (t < RR - 1) ? s_v[t + 1] : 0.f;
    float r  = klr + ((t == g_vlp[b]) ? g_score[b] : 0.f);
    float u  = r + GAMMA_C * vn - v;    // adv[t] = u[t] + c*adv[t+1]
    s_a[t] = u;
    __syncthreads();

    float c = GAMMA_C * LMBDA_C;        // 0.9405
    #pragma unroll
    for (int d = 1; d < RR; d <<= 1) {
        float oth = (t + d < RR) ? s_a[t + d] : 0.f;
        __syncthreads();
        s_a[t] += c * oth;
        __syncthreads();
        c *= c;
    }
    float adv = s_a[t];
    g_adv[idx] = adv;
    out[OFF_RET + idx] = adv + v;

    // masked partial sums for whitening (double, deterministic per batch)
    int m = (pad[idx] == 0);
    double da = m ? (double)adv : 0.0;
    double dq = m ? (double)adv * (double)adv : 0.0;
    double dn = m ? 1.0 : 0.0;
    #pragma unroll
    for (int o = 16; o; o >>= 1) {
        da += __shfl_down_sync(0xffffffffu, da, o);
        dq += __shfl_down_sync(0xffffffffu, dq, o);
        dn += __shfl_down_sync(0xffffffffu, dn, o);
    }
    int lane = t & 31, warp = t >> 5;
    if (lane == 0) { s_red[0][warp] = da; s_red[1][warp] = dq; s_red[2][warp] = dn; }
    __syncthreads();
    if (t == 0) {
        double S = 0, Q2 = 0, N = 0;
        #pragma unroll
        for (int i = 0; i < 32; i++) { S += s_red[0][i]; Q2 += s_red[1][i]; N += s_red[2][i]; }
        g_psum[b] = S; g_psq[b] = Q2; g_pcnt[b] = N;
    }
}

// ========================================================================
// K4: masked whitening of advantages. 32 blocks x 1024. Each block sums
// the 32 per-batch partials (cheap, deterministic), then normalizes.
// ========================================================================
__global__ void __launch_bounds__(1024) k_whiten(
    const int* __restrict__ pad, float* __restrict__ out)
{
    __shared__ double sh_mean, sh_inv;
    if (threadIdx.x == 0) {
        double S = 0, Q2 = 0, N = 0;
        #pragma unroll
        for (int i = 0; i < BB; i++) { S += g_psum[i]; Q2 += g_psq[i]; N += g_pcnt[i]; }
        double mean = S / N;
        double var  = (Q2 / N - mean * mean) * (N / (N - 1.0));
        sh_mean = mean;
        sh_inv  = 1.0 / sqrt(var + 1e-8);
    }
    __syncthreads();
    int idx = blockIdx.x * 1024 + threadIdx.x;
    float adv = g_adv[idx];
    float w = (float)(((double)adv - sh_mean) * sh_inv);
    out[OFF_ADV + idx] = (pad[idx] == 0) ? w : 0.f;
}

// ========================================================================
extern "C" void kernel_launch(void* const* d_in, const int* in_sizes, int n_in,
                              void* d_out, int out_size) {
    const float* hidden = (const float*)d_in[0];
    const float* wb     = (const float*)d_in[1];
    const float* wa     = (const float*)d_in[2];
    const float* gen    = (const float*)d_in[3];
    const float* ref    = (const float*)d_in[4];
    const int*   pad    = (const int*)d_in[5];   // JAX bool -> int32 marshalling
    float* out = (float*)d_out;

    k_meta  <<<1,            1024>>>(pad, out);
    k_values<<<BB * RR / 8,   256>>>(hidden, wb, wa, pad, out);
    k_scores<<<BB,            256>>>(hidden, wb, out);
    k_gae   <<<BB,           1024>>>(gen, ref, pad, out);
    k_whiten<<<BB,           1024>>>(pad, out);
}